// round 1
// baseline (speedup 1.0000x reference)
#include <cuda_runtime.h>

#define BATCH 2
#define SEQ   2048
#define MEMN  256
#define DIM   1024
#define HEADS 16
#define DH    64
#define ROWS  (BATCH*SEQ)     // 4096
#define MROWS (BATCH*MEMN)    // 512
#define KTOT  (SEQ+MEMN)      // 2304

// -------- scratch (static device globals; no allocation allowed) --------
static __device__ float g_xn [ROWS * DIM];
static __device__ float g_q  [ROWS * DIM];
static __device__ float g_kv [ROWS * 2 * DIM];
static __device__ float g_mem[MROWS * DIM];
static __device__ float g_att[ROWS * DIM];

// =======================================================================
// LayerNorm: one block per row, 256 threads, one float4 per thread
// =======================================================================
__global__ void __launch_bounds__(256) ln_kernel(
    const float* __restrict__ x, const float* __restrict__ gamma,
    const float* __restrict__ beta, float* __restrict__ out)
{
    const int row = blockIdx.x;
    const int t   = threadIdx.x;
    float4 v = ((const float4*)(x + (size_t)row * DIM))[t];
    float s  = v.x + v.y + v.z + v.w;
    float ss = v.x*v.x + v.y*v.y + v.z*v.z + v.w*v.w;
    #pragma unroll
    for (int o = 16; o > 0; o >>= 1) {
        s  += __shfl_xor_sync(0xffffffffu, s,  o);
        ss += __shfl_xor_sync(0xffffffffu, ss, o);
    }
    __shared__ float sums[8], sqs[8];
    if ((t & 31) == 0) { sums[t >> 5] = s; sqs[t >> 5] = ss; }
    __syncthreads();
    s = 0.f; ss = 0.f;
    #pragma unroll
    for (int i = 0; i < 8; i++) { s += sums[i]; ss += sqs[i]; }
    const float mean = s * (1.0f / DIM);
    const float var  = ss * (1.0f / DIM) - mean * mean;
    const float rstd = rsqrtf(var + 1e-5f);
    float4 g4 = ((const float4*)gamma)[t];
    float4 b4 = ((const float4*)beta)[t];
    float4 o;
    o.x = (v.x - mean) * rstd * g4.x + b4.x;
    o.y = (v.y - mean) * rstd * g4.y + b4.y;
    o.z = (v.z - mean) * rstd * g4.z + b4.z;
    o.w = (v.w - mean) * rstd * g4.w + b4.w;
    ((float4*)(out + (size_t)row * DIM))[t] = o;
}

// =======================================================================
// SGEMM: C[M,N] = A[M,K] @ B[K,N] (+bias). 128x128 block, BK=8,
// 256 threads, 8x8 microtile. A staged transposed in smem.
// =======================================================================
template <bool HAS_BIAS>
__global__ void __launch_bounds__(256) sgemm_kernel(
    const float* __restrict__ A, const float* __restrict__ B,
    const float* __restrict__ bias, float* __restrict__ C,
    int M, int N, int K)
{
    __shared__ float As[8][128];
    __shared__ float Bs[8][128];

    const int tid = threadIdx.x;
    const int m0 = blockIdx.y * 128, n0 = blockIdx.x * 128;
    const int rowA = tid >> 1, colA = (tid & 1) * 4;
    const int rowB = tid >> 5, colB = (tid & 31) * 4;
    const float* Ap = A + (size_t)(m0 + rowA) * K + colA;
    const float* Bp = B + (size_t)rowB * N + n0 + colB;
    const int tr = (tid >> 4) * 8, tc = (tid & 15) * 8;

    float acc[8][8];
    #pragma unroll
    for (int i = 0; i < 8; i++)
        #pragma unroll
        for (int j = 0; j < 8; j++) acc[i][j] = 0.f;

    for (int k0 = 0; k0 < K; k0 += 8) {
        float4 a4 = *(const float4*)(Ap + k0);
        float4 b4 = *(const float4*)(Bp + (size_t)k0 * N);
        As[colA + 0][rowA] = a4.x;
        As[colA + 1][rowA] = a4.y;
        As[colA + 2][rowA] = a4.z;
        As[colA + 3][rowA] = a4.w;
        *(float4*)&Bs[rowB][colB] = b4;
        __syncthreads();
        #pragma unroll
        for (int k = 0; k < 8; k++) {
            float rm[8], rn[8];
            *(float4*)&rm[0] = *(const float4*)&As[k][tr];
            *(float4*)&rm[4] = *(const float4*)&As[k][tr + 4];
            *(float4*)&rn[0] = *(const float4*)&Bs[k][tc];
            *(float4*)&rn[4] = *(const float4*)&Bs[k][tc + 4];
            #pragma unroll
            for (int i = 0; i < 8; i++)
                #pragma unroll
                for (int j = 0; j < 8; j++)
                    acc[i][j] += rm[i] * rn[j];
        }
        __syncthreads();
    }

    float bb[8];
    if (HAS_BIAS) {
        #pragma unroll
        for (int j = 0; j < 8; j++) bb[j] = bias[n0 + tc + j];
    }
    #pragma unroll
    for (int i = 0; i < 8; i++) {
        float* Crow = C + (size_t)(m0 + tr + i) * N + n0 + tc;
        #pragma unroll
        for (int j4 = 0; j4 < 8; j4 += 4) {
            float4 o;
            o.x = acc[i][j4 + 0]; o.y = acc[i][j4 + 1];
            o.z = acc[i][j4 + 2]; o.w = acc[i][j4 + 3];
            if (HAS_BIAS) { o.x += bb[j4+0]; o.y += bb[j4+1]; o.z += bb[j4+2]; o.w += bb[j4+3]; }
            *(float4*)(Crow + j4) = o;
        }
    }
}

// =======================================================================
// Flash attention, fp32. Grid: (SEQ/64, HEADS, BATCH). 256 threads = 8
// warps; warp w owns query rows w*8..w*8+7; lane owns columns {2l, 2l+1}.
// K tile stored transposed [d][c] with XOR swizzle (conflict-free STS+LDS),
// V reuses the same smem buffer after QK^T. Smem = 48KB exactly.
// =======================================================================
__device__ __forceinline__ int swz(int d) { return ((d + (d >> 2)) * 2) & 63; }

__global__ void __launch_bounds__(256) attn_kernel(
    const float* __restrict__ Q, const float* __restrict__ KV,
    const float* __restrict__ MEMP, float* __restrict__ OUT)
{
    __shared__ float Qs[64 * 64];
    __shared__ float KVs[64 * 64];
    __shared__ float Ps[8][512];

    const int tid  = threadIdx.x;
    const int lane = tid & 31;
    const int warp = tid >> 5;
    const int qt = blockIdx.x, h = blockIdx.y, b = blockIdx.z;
    const int hcol  = h * DH;
    const int qrow0 = b * SEQ + qt * 64;
    const float scale = 0.125f;  // DH^-0.5

    // load Q tile (pre-scaled)
    #pragma unroll
    for (int i = 0; i < 4; i++) {
        int f = tid + i * 256;
        int r = f >> 4, d4 = (f & 15) * 4;
        float4 v = *(const float4*)(Q + (size_t)(qrow0 + r) * DIM + hcol + d4);
        v.x *= scale; v.y *= scale; v.z *= scale; v.w *= scale;
        *(float4*)&Qs[r * 64 + d4] = v;
    }

    float m[8], l[8], acc0[8], acc1[8];
    #pragma unroll
    for (int r = 0; r < 8; r++) { m[r] = -1e30f; l[r] = 0.f; acc0[r] = 0.f; acc1[r] = 0.f; }

    const int c0  = lane * 2;
    const int wr0 = warp * 8;

    for (int jt = 0; jt < KTOT / 64; jt++) {
        const int j0 = jt * 64;
        float4 kreg[4], vreg[4];
        // global loads for K & V tile (V held in regs through QK phase)
        #pragma unroll
        for (int i = 0; i < 4; i++) {
            int f = tid + i * 256;
            int c = f >> 4, d4 = (f & 15) * 4;
            if (j0 < SEQ) {
                const float* base = KV + (size_t)(b * SEQ + j0 + c) * (2 * DIM) + hcol + d4;
                kreg[i] = *(const float4*)base;
                vreg[i] = *(const float4*)(base + DIM);
            } else {
                const float* base = MEMP + (size_t)(b * MEMN + j0 - SEQ + c) * DIM + hcol + d4;
                kreg[i] = *(const float4*)base;
                vreg[i] = kreg[i];   // mem serves as both k and v
            }
        }
        __syncthreads();   // previous tile's PV done with KVs
        #pragma unroll
        for (int i = 0; i < 4; i++) {
            int f = tid + i * 256;
            int c = f >> 4, d4 = (f & 15) * 4;
            KVs[(d4 + 0) * 64 + (c ^ swz(d4 + 0))] = kreg[i].x;
            KVs[(d4 + 1) * 64 + (c ^ swz(d4 + 1))] = kreg[i].y;
            KVs[(d4 + 2) * 64 + (c ^ swz(d4 + 2))] = kreg[i].z;
            KVs[(d4 + 3) * 64 + (c ^ swz(d4 + 3))] = kreg[i].w;
        }
        __syncthreads();

        // ---- S = Q K^T (scaled) ----
        float s0[8], s1[8];
        #pragma unroll
        for (int r = 0; r < 8; r++) { s0[r] = 0.f; s1[r] = 0.f; }
        #pragma unroll
        for (int d4 = 0; d4 < 64; d4 += 4) {
            float2 kk[4];
            #pragma unroll
            for (int i = 0; i < 4; i++)
                kk[i] = *(const float2*)&KVs[(d4 + i) * 64 + (c0 ^ swz(d4 + i))];
            #pragma unroll
            for (int r = 0; r < 8; r++) {
                float4 qv = *(const float4*)&Qs[(wr0 + r) * 64 + d4];
                s0[r] += qv.x * kk[0].x; s0[r] += qv.y * kk[1].x;
                s0[r] += qv.z * kk[2].x; s0[r] += qv.w * kk[3].x;
                s1[r] += qv.x * kk[0].y; s1[r] += qv.y * kk[1].y;
                s1[r] += qv.z * kk[2].y; s1[r] += qv.w * kk[3].y;
            }
        }

        // ---- online softmax (per warp-row, warp shfl reductions) ----
        #pragma unroll
        for (int r = 0; r < 8; r++) {
            float tmax = fmaxf(s0[r], s1[r]);
            #pragma unroll
            for (int o = 16; o > 0; o >>= 1)
                tmax = fmaxf(tmax, __shfl_xor_sync(0xffffffffu, tmax, o));
            float mn = fmaxf(m[r], tmax);
            float p0 = __expf(s0[r] - mn);
            float p1 = __expf(s1[r] - mn);
            float rs = p0 + p1;
            #pragma unroll
            for (int o = 16; o > 0; o >>= 1)
                rs += __shfl_xor_sync(0xffffffffu, rs, o);
            float al = __expf(m[r] - mn);
            l[r] = l[r] * al + rs;
            m[r] = mn;
            acc0[r] *= al; acc1[r] *= al;
            *(float2*)&Ps[warp][r * 64 + c0] = make_float2(p0, p1);
        }

        __syncthreads();   // all warps done reading K^T from KVs
        // stage V (natural [c][d] layout) into the same buffer
        #pragma unroll
        for (int i = 0; i < 4; i++) {
            int f = tid + i * 256;
            int c = f >> 4, d4 = (f & 15) * 4;
            *(float2*)&KVs[c * 64 + d4]     = make_float2(vreg[i].x, vreg[i].y);
            *(float2*)&KVs[c * 64 + d4 + 2] = make_float2(vreg[i].z, vreg[i].w);
        }
        __syncthreads();

        // ---- acc += P @ V ----
        #pragma unroll
        for (int c4 = 0; c4 < 64; c4 += 4) {
            float2 vv[4];
            #pragma unroll
            for (int i = 0; i < 4; i++)
                vv[i] = *(const float2*)&KVs[(c4 + i) * 64 + c0];
            #pragma unroll
            for (int r = 0; r < 8; r++) {
                float4 p = *(const float4*)&Ps[warp][r * 64 + c4];
                acc0[r] += p.x * vv[0].x; acc0[r] += p.y * vv[1].x;
                acc0[r] += p.z * vv[2].x; acc0[r] += p.w * vv[3].x;
                acc1[r] += p.x * vv[0].y; acc1[r] += p.y * vv[1].y;
                acc1[r] += p.z * vv[2].y; acc1[r] += p.w * vv[3].y;
            }
        }
    }

    #pragma unroll
    for (int r = 0; r < 8; r++) {
        float inv = 1.0f / l[r];
        *(float2*)&OUT[(size_t)(qrow0 + wr0 + r) * DIM + hcol + c0] =
            make_float2(acc0[r] * inv, acc1[r] * inv);
    }
}

// =======================================================================
// launch
// =======================================================================
extern "C" void kernel_launch(void* const* d_in, const int* in_sizes, int n_in,
                              void* d_out, int out_size)
{
    const float* x        = (const float*)d_in[0];
    const float* memories = (const float*)d_in[1];
    const float* ln_g     = (const float*)d_in[2];
    const float* ln_b     = (const float*)d_in[3];
    const float* Wq       = (const float*)d_in[4];
    const float* Wkv      = (const float*)d_in[5];
    const float* Wm       = (const float*)d_in[6];
    const float* Wo       = (const float*)d_in[7];
    const float* bo       = (const float*)d_in[8];
    float* out = (float*)d_out;

    float *p_xn, *p_q, *p_kv, *p_mem, *p_att;
    cudaGetSymbolAddress((void**)&p_xn,  g_xn);
    cudaGetSymbolAddress((void**)&p_q,   g_q);
    cudaGetSymbolAddress((void**)&p_kv,  g_kv);
    cudaGetSymbolAddress((void**)&p_mem, g_mem);
    cudaGetSymbolAddress((void**)&p_att, g_att);

    // 1. LayerNorm(x) -> xn
    ln_kernel<<<ROWS, 256>>>(x, ln_g, ln_b, p_xn);

    // 2. projections
    sgemm_kernel<false><<<dim3(DIM / 128,     ROWS / 128),  256>>>(p_xn, Wq,  nullptr, p_q,  ROWS,  DIM,     DIM);
    sgemm_kernel<false><<<dim3(2 * DIM / 128, ROWS / 128),  256>>>(p_xn, Wkv, nullptr, p_kv, ROWS,  2 * DIM, DIM);
    sgemm_kernel<false><<<dim3(DIM / 128,     MROWS / 128), 256>>>(memories, Wm, nullptr, p_mem, MROWS, DIM, DIM);

    // 3. attention
    attn_kernel<<<dim3(SEQ / 64, HEADS, BATCH), 256>>>(p_q, p_kv, p_mem, p_att);

    // 4. output projection + bias -> d_out
    sgemm_kernel<true><<<dim3(DIM / 128, ROWS / 128), 256>>>(p_att, Wo, bo, out, ROWS, DIM, DIM);
}